// round 9
// baseline (speedup 1.0000x reference)
#include <cuda_runtime.h>
#include <cstdint>

#define TT     224
#define HH     128
#define BB     64
#define SS     20
#define NN     1280      // BB*SS
#define G4     4         // sequences per LSTM CTA
#define NG     320       // NN/G4
#define NINTER 64
#define KSPLIT 8
#define TM     32        // seq tile in feats GEMM
#define TCHUNK 28        // 224/KSPLIT timesteps per k-split

typedef unsigned long long u64;

// ---------------- scratch (static device globals; no runtime allocation) ---------
__device__ __align__(16) float g_hs[(size_t)NN * TT * HH];   // [n][t][h]
__device__ int   g_len[NN];
__device__ int   g_order[NN];
__device__ int   g_hist[256];
__device__ int   g_off[256];
__device__ __align__(16) float g_Wk[512 * 128];   // [p2][q*4+g] float4 = W[g*128+q][4p2..4p2+3]
__device__ __align__(16) float g_psum[(size_t)KSPLIT * NN * NINTER];

// ---------------- helpers ----------------
__device__ __forceinline__ u64 ffma2(u64 a, u64 b, u64 c) {
    u64 d;
    asm("fma.rn.f32x2 %0, %1, %2, %3;" : "=l"(d) : "l"(a), "l"(b), "l"(c));
    return d;
}
__device__ __forceinline__ float f2lo(u64 v) { return __uint_as_float((unsigned)(v & 0xffffffffull)); }
__device__ __forceinline__ float f2hi(u64 v) { return __uint_as_float((unsigned)(v >> 32)); }
__device__ __forceinline__ float sigf(float v) {
    return __fdividef(1.0f, 1.0f + __expf(-v));
}
__device__ __forceinline__ float tanh_(float v) {
    float e = __expf(-2.0f * v);
    return __fdividef(1.0f - e, 1.0f + e);
}
// branchless 4-way select with constant indices (stays in registers)
__device__ __forceinline__ float pick4(float a0, float a1, float a2, float a3, int i) {
    float v = a0;
    v = (i == 1) ? a1 : v;
    v = (i == 2) ? a2 : v;
    v = (i == 3) ? a3 : v;
    return v;
}

// ---------------- kernel 0: zero histogram ---------------------------------------
__global__ void k_zero_hist() {
    if (threadIdx.x < 256) g_hist[threadIdx.x] = 0;
}

// ---------------- kernel 1: ragged lengths + histogram ---------------------------
__global__ void k_lens(const float* __restrict__ x) {
    int n = blockIdx.x;
    const float* xs = x + (size_t)n * TT;
    int first = 1 << 30;
    for (int t = threadIdx.x; t < TT; t += 32)
        if (xs[t] == 0.0f) first = min(first, t);
    #pragma unroll
    for (int o = 16; o; o >>= 1)
        first = min(first, __shfl_xor_sync(0xffffffffu, first, o));
    if (threadIdx.x == 0) {
        int len = (first == 0 || first >= TT) ? TT : (first + 1);
        g_len[n] = len;
        atomicAdd(&g_hist[len], 1);
    }
}

// ---------------- kernel 2: prefix sum over hist ---------------------------------
__global__ void k_prefix() {
    if (threadIdx.x == 0) {
        int acc = 0;
        for (int i = 0; i < 256; i++) { g_off[i] = acc; acc += g_hist[i]; }
    }
}

// ---------------- kernel 3: counting-sort scatter (ascending by len) -------------
__global__ void k_scatter() {
    int n = blockIdx.x * blockDim.x + threadIdx.x;
    if (n < NN) {
        int pos = atomicAdd(&g_off[g_len[n]], 1);
        g_order[pos] = n;
    }
}

// ---------------- kernel 4: repack W_hh ------------------------------------------
// dst float4 j -> (p2 = j>>9, slot = j&511, with slot = q*4+g), src row = g*128+q
__global__ void k_wt(const float* __restrict__ Whh) {
    int j = blockIdx.x * blockDim.x + threadIdx.x;   // 0..16383
    int g  = j & 3;
    int q  = (j >> 2) & 127;
    int p2 = j >> 9;
    int r  = g * 128 + q;
    float4 v = ((const float4*)Whh)[r * 32 + p2];
    ((float4*)g_Wk)[j] = v;   // j == p2*512 + q*4 + g
}

// ---------------- kernel 5: LSTM (512 threads, 1 gate-row/thread) ----------------
// tid = q*4+g : gate g of hidden unit q, i.e. row r = g*128+q. Quad (lanes 4q..4q+3)
// holds the 4 gates of unit q; gate exchange via shfl.xor masks 1,2,3.
// Thread owns cell (unit q, sequence g).
// dynamic smem:
//   [0, 163840)        sW  : float4[20*512]   weight k-quads p2=0..19, slot-ordered
//   [163840, 167936)   shf : float[2][4][128] double-buffered h  [buf][seq][unit]
//   [167936, 171520)   sx  : float[4][224]
#define LSTM_SMEM 171520
__global__ void __launch_bounds__(512, 1) k_lstm(
    const float* __restrict__ x, const float* __restrict__ Wih,
    const float* __restrict__ bih, const float* __restrict__ bhh)
{
    extern __shared__ __align__(16) char dyn[];
    ulonglong2* sW = (ulonglong2*)dyn;
    float* shf = (float*)(dyn + 163840);
    float* sx  = (float*)(dyn + 167936);
    __shared__ int sn[G4], sl[G4];

    int tid = threadIdx.x;
    int g = tid & 3;
    int q = tid >> 2;
    int r = g * 128 + q;

    int grp = (NG - 1) - blockIdx.x;   // longest groups first
    if (tid < G4) {
        int n = g_order[grp * G4 + tid];
        sn[tid] = n;
        sl[tid] = g_len[n];
    }

    // stage smem weight part (p2 = 0..19), already slot-ordered: warp reads contiguous
    const float4* Wk4 = (const float4*)g_Wk;
    float4* sW4 = (float4*)sW;
    for (int i = tid; i < 20 * 512; i += 512) sW4[i] = Wk4[i];
    // zero both h buffers
    for (int i = tid; i < 1024; i += 512) shf[i] = 0.0f;

    // register weight part (p2 = 20..31)
    ulonglong2 wr[12];
    const ulonglong2* Wk2 = (const ulonglong2*)g_Wk;
    #pragma unroll
    for (int i = 0; i < 12; i++)
        wr[i] = Wk2[(size_t)(20 + i) * 512 + tid];

    float wi = Wih[r];
    float bs = bih[r] + bhh[r];

    __syncthreads();
    int l0 = sl[0], l1 = sl[1], l2 = sl[2], l3 = sl[3];
    int maxlen = max(max(l0, l1), max(l2, l3));
    int mylen = sl[g];

    #pragma unroll
    for (int m = 0; m < G4; m++)
        for (int t = tid; t < TT; t += 512) sx[m * TT + t] = x[(size_t)sn[m] * TT + t];

    float* hsout = g_hs + (size_t)sn[g] * TT * HH + q;
    float c = 0.0f;
    __syncthreads();

    for (int t = 0; t < maxlen; t++) {
        int cur = t & 1, nxt = cur ^ 1;
        const ulonglong2* hb = (const ulonglong2*)(shf + cur * 512);

        u64 A0 = 0, A1 = 0, A2 = 0, A3 = 0;   // my row x seqs 0..3

        #pragma unroll 4
        for (int p2 = 0; p2 < 20; p2++) {
            ulonglong2 w = sW[p2 * 512 + tid];
            ulonglong2 h0 = hb[p2], h1 = hb[32 + p2], h2 = hb[64 + p2], h3 = hb[96 + p2];
            A0 = ffma2(w.x, h0.x, A0); A0 = ffma2(w.y, h0.y, A0);
            A1 = ffma2(w.x, h1.x, A1); A1 = ffma2(w.y, h1.y, A1);
            A2 = ffma2(w.x, h2.x, A2); A2 = ffma2(w.y, h2.y, A2);
            A3 = ffma2(w.x, h3.x, A3); A3 = ffma2(w.y, h3.y, A3);
        }
        #pragma unroll
        for (int i = 0; i < 12; i++) {
            int p2 = 20 + i;
            ulonglong2 w = wr[i];
            ulonglong2 h0 = hb[p2], h1 = hb[32 + p2], h2 = hb[64 + p2], h3 = hb[96 + p2];
            A0 = ffma2(w.x, h0.x, A0); A0 = ffma2(w.y, h0.y, A0);
            A1 = ffma2(w.x, h1.x, A1); A1 = ffma2(w.y, h1.y, A1);
            A2 = ffma2(w.x, h2.x, A2); A2 = ffma2(w.y, h2.y, A2);
            A3 = ffma2(w.x, h3.x, A3); A3 = ffma2(w.y, h3.y, A3);
        }

        float xt0 = sx[t], xt1 = sx[TT + t], xt2 = sx[2 * TT + t], xt3 = sx[3 * TT + t];
        // P[s] = pre-activation of my gate-row for sequence s
        float P0 = f2lo(A0) + f2hi(A0) + xt0 * wi + bs;
        float P1 = f2lo(A1) + f2hi(A1) + xt1 * wi + bs;
        float P2 = f2lo(A2) + f2hi(A2) + xt2 * wi + bs;
        float P3 = f2lo(A3) + f2hi(A3) + xt3 * wi + bs;

        // quad gate exchange: lane g sends P[g^m] on mask m; receives P_{g^m}[g]
        float s1 = pick4(P0, P1, P2, P3, g ^ 1);
        float s2 = pick4(P0, P1, P2, P3, g ^ 2);
        float s3 = pick4(P0, P1, P2, P3, g ^ 3);
        float a0 = pick4(P0, P1, P2, P3, g);                 // gate g,   seq g (own)
        float a1 = __shfl_xor_sync(0xffffffffu, s1, 1);      // gate g^1, seq g
        float a2 = __shfl_xor_sync(0xffffffffu, s2, 2);      // gate g^2, seq g
        float a3 = __shfl_xor_sync(0xffffffffu, s3, 3);      // gate g^3, seq g

        // gate j (0=i,1=f,2=g,3=o) for seq g is arr[j^g]
        float gi = pick4(a0, a1, a2, a3, 0 ^ g);
        float gf = pick4(a0, a1, a2, a3, 1 ^ g);
        float gc = pick4(a0, a1, a2, a3, 2 ^ g);
        float go = pick4(a0, a1, a2, a3, 3 ^ g);

        c = sigf(gf) * c + sigf(gi) * tanh_(gc);
        float hv = sigf(go) * tanh_(c);
        shf[nxt * 512 + g * 128 + q] = hv;
        if (t < mylen) hsout[(size_t)t * HH] = hv;

        __syncthreads();
    }

    // zero masked tails so the feats GEMM can ignore lengths
    for (int t = mylen; t < TT; t++) hsout[(size_t)t * HH] = 0.0f;
}

// ---------------- kernel 6: feats GEMM (split-K, tiled, f32x2) -------------------
// psum[kz][n][j] = sum_{t in chunk} sum_h hs[n][t][h] * W1[j][t*128+h]
__global__ void __launch_bounds__(256) k_feats(const float* __restrict__ W1) {
    __shared__ __align__(16) float sh_hs[TM][HH + 4];     // padded: conflict-free
    __shared__ __align__(16) float sh_w[NINTER][HH];

    int tile = blockIdx.x;        // 0..39
    int kz = blockIdx.y;          // 0..7
    int tid = threadIdx.x;
    int s0 = tid & 15;            // rows s0 and s0+16
    int j0 = (tid >> 4) * 4;      // 4 inter cols
    u64 a0[4] = {0, 0, 0, 0};
    u64 a1[4] = {0, 0, 0, 0};

    int t0 = kz * TCHUNK;
    for (int tt = 0; tt < TCHUNK; tt++) {
        int t = t0 + tt;
        __syncthreads();
        for (int i = tid; i < TM * 32; i += 256) {
            int s = i >> 5, kq = i & 31;
            ((float4*)&sh_hs[s][0])[kq] =
                ((const float4*)(g_hs + ((size_t)(tile * TM + s) * TT + t) * HH))[kq];
        }
        for (int i = tid; i < NINTER * 32; i += 256) {
            int j = i >> 5, kq = i & 31;
            ((float4*)&sh_w[j][0])[kq] =
                ((const float4*)(W1 + (size_t)j * (TT * HH) + (size_t)t * HH))[kq];
        }
        __syncthreads();
        #pragma unroll 4
        for (int kq = 0; kq < 32; kq++) {
            ulonglong2 hA = ((const ulonglong2*)&sh_hs[s0][0])[kq];
            ulonglong2 hB = ((const ulonglong2*)&sh_hs[s0 + 16][0])[kq];
            #pragma unroll
            for (int c = 0; c < 4; c++) {
                ulonglong2 w = ((const ulonglong2*)&sh_w[j0 + c][0])[kq];
                a0[c] = ffma2(hA.x, w.x, a0[c]); a0[c] = ffma2(hA.y, w.y, a0[c]);
                a1[c] = ffma2(hB.x, w.x, a1[c]); a1[c] = ffma2(hB.y, w.y, a1[c]);
            }
        }
    }
    int srow = tile * TM;
    size_t baseA = ((size_t)kz * NN + (srow + s0)) * NINTER + j0;
    size_t baseB = ((size_t)kz * NN + (srow + s0 + 16)) * NINTER + j0;
    #pragma unroll
    for (int c = 0; c < 4; c++) {
        g_psum[baseA + c] = f2lo(a0[c]) + f2hi(a0[c]);
        g_psum[baseB + c] = f2lo(a1[c]) + f2hi(a1[c]);
    }
}

// ---------------- kernel 7: reduce split-K + bias + final linear -----------------
__global__ void __launch_bounds__(256) k_final(
    const float* __restrict__ b1, const float* __restrict__ W2,
    const float* __restrict__ b2, float* __restrict__ out)
{
    __shared__ float sf[SS * NINTER];   // 1280 feats for this batch
    __shared__ float r0[256], r1[256];
    int b = blockIdx.x, tid = threadIdx.x;

    for (int i = tid; i < SS * NINTER; i += 256) {
        int s = i / NINTER, j = i % NINTER;
        size_t nq = (size_t)b * SS + s;
        float v = b1[j];
        #pragma unroll
        for (int kz = 0; kz < KSPLIT; kz++)
            v += g_psum[((size_t)kz * NN + nq) * NINTER + j];
        sf[i] = v;
    }
    __syncthreads();
    float p0 = 0.f, p1 = 0.f;
    for (int i = tid; i < SS * NINTER; i += 256) {
        float f = sf[i];
        p0 += f * W2[i];
        p1 += f * W2[SS * NINTER + i];
    }
    r0[tid] = p0; r1[tid] = p1;
    __syncthreads();
    for (int off = 128; off; off >>= 1) {
        if (tid < off) { r0[tid] += r0[tid + off]; r1[tid] += r1[tid + off]; }
        __syncthreads();
    }
    if (tid == 0) {
        out[b * 2 + 0] = r0[0] + b2[0];
        out[b * 2 + 1] = r1[0] + b2[1];
    }
}

// ---------------- launch ----------------------------------------------------------
extern "C" void kernel_launch(void* const* d_in, const int* in_sizes, int n_in,
                              void* d_out, int out_size)
{
    const float* x   = (const float*)d_in[0];
    // d_in[1] = metadata (unused by the reference computation)
    const float* Wih = (const float*)d_in[2];
    const float* Whh = (const float*)d_in[3];
    const float* bih = (const float*)d_in[4];
    const float* bhh = (const float*)d_in[5];
    const float* W1  = (const float*)d_in[6];
    const float* b1  = (const float*)d_in[7];
    const float* W2  = (const float*)d_in[8];
    const float* b2  = (const float*)d_in[9];
    float* out = (float*)d_out;

    cudaFuncSetAttribute(k_lstm, cudaFuncAttributeMaxDynamicSharedMemorySize, LSTM_SMEM);

    k_zero_hist<<<1, 256>>>();
    k_lens<<<NN, 32>>>(x);
    k_prefix<<<1, 32>>>();
    k_scatter<<<5, 256>>>();
    k_wt<<<64, 256>>>(Whh);
    k_lstm<<<NG, 512, LSTM_SMEM>>>(x, Wih, bih, bhh);
    k_feats<<<dim3(40, KSPLIT), 256>>>(W1);
    k_final<<<BB, 256>>>(b1, W2, b2, out);
}

// round 10
// speedup vs baseline: 1.0287x; 1.0287x over previous
#include <cuda_runtime.h>
#include <cstdint>

#define TT     224
#define HH     128
#define BB     64
#define SS     20
#define NN     1280      // BB*SS
#define GM     8         // sequences per LSTM CTA
#define NGRP   160       // NN/GM
#define NINTER 64
#define KSPLIT 8
#define TM     32        // seq tile in feats GEMM
#define TCHUNK 28        // 224/KSPLIT timesteps per k-split

typedef unsigned long long u64;

// ---------------- scratch (static device globals; no runtime allocation) ---------
__device__ __align__(16) float g_hs[(size_t)NN * TT * HH];   // [n][t][h]
__device__ int   g_len[NN];
__device__ int   g_order[NN];
__device__ __align__(16) float g_Wk[512 * 128];              // [p2][r] float4: W[r][4p2..4p2+3]
__device__ __align__(16) float g_psum[(size_t)KSPLIT * NN * NINTER];

// ---------------- helpers ----------------
__device__ __forceinline__ u64 ffma2(u64 a, u64 b, u64 c) {
    u64 d;
    asm("fma.rn.f32x2 %0, %1, %2, %3;" : "=l"(d) : "l"(a), "l"(b), "l"(c));
    return d;
}
__device__ __forceinline__ float f2lo(u64 v) { return __uint_as_float((unsigned)(v & 0xffffffffull)); }
__device__ __forceinline__ float f2hi(u64 v) { return __uint_as_float((unsigned)(v >> 32)); }
__device__ __forceinline__ float sigf(float v) {
    return __fdividef(1.0f, 1.0f + __expf(-v));
}
__device__ __forceinline__ float tanh_(float v) {
    float e = __expf(-2.0f * v);
    return __fdividef(1.0f - e, 1.0f + e);
}

// ---------------- kernel 1: ragged lengths ---------------------------------------
// reference: maxes = argmax(x==0, axis=time); len = (maxes==0) ? T : maxes+1
__global__ void k_lens(const float* __restrict__ x) {
    int n = blockIdx.x;
    const float* xs = x + (size_t)n * TT;
    int first = 1 << 30;
    for (int t = threadIdx.x; t < TT; t += 32)
        if (xs[t] == 0.0f) first = min(first, t);
    #pragma unroll
    for (int o = 16; o; o >>= 1)
        first = min(first, __shfl_xor_sync(0xffffffffu, first, o));
    if (threadIdx.x == 0)
        g_len[n] = (first == 0 || first >= TT) ? TT : (first + 1);
}

// ---------------- kernel 2: single-CTA counting sort by length -------------------
__global__ void __launch_bounds__(256) k_sort() {
    __shared__ int hist[256];
    __shared__ int off[256];
    int tid = threadIdx.x;
    hist[tid] = 0;
    __syncthreads();
    for (int n = tid; n < NN; n += 256) atomicAdd(&hist[g_len[n]], 1);
    __syncthreads();
    if (tid == 0) {
        int acc = 0;
        for (int i = 0; i < 256; i++) { off[i] = acc; acc += hist[i]; }
    }
    __syncthreads();
    for (int n = tid; n < NN; n += 256) {
        int pos = atomicAdd(&off[g_len[n]], 1);
        g_order[pos] = n;
    }
}

// ---------------- kernel 3: repack W_hh: g_Wk[p2*512 + r] = W[r][4p2..4p2+3] -----
__global__ void k_wt(const float* __restrict__ Whh) {
    int i = blockIdx.x * blockDim.x + threadIdx.x;   // 0..16383
    int r  = i & 511;
    int p2 = i >> 9;
    float4 v = ((const float4*)Whh)[r * 32 + p2];
    ((float4*)g_Wk)[p2 * 512 + r] = v;
}

// ---------------- kernel 4: LSTM (8 seqs/CTA, 256 threads, 2 gate-rows/thread) ---
// thread tid: rows r0 = tid (gate g0 = tid>>7), r1 = tid+256 (gate g0+2); unit u = tid&127.
// cells owned: (u, seq m) for m = g0, g0+2, g0+4, g0+6.
// dynamic smem:
//   [0, 180224)        sW   : float4[22*512]      weight k-quads p2=0..21
//   [180224, 188416)   shf  : float[2][8][128]    double-buffered h
//   [188416, 204800)   spre : float[4][8][128]    gate pre-activations
//   [204800, 211968)   sx   : float[8][224]
#define LSTM_SMEM 211968
__global__ void __launch_bounds__(256, 1) k_lstm(
    const float* __restrict__ x, const float* __restrict__ Wih,
    const float* __restrict__ bih, const float* __restrict__ bhh)
{
    extern __shared__ __align__(16) char dyn[];
    ulonglong2* sW = (ulonglong2*)dyn;
    float* shf  = (float*)(dyn + 180224);
    float* spre = (float*)(dyn + 188416);
    float* sx   = (float*)(dyn + 204800);
    __shared__ int sn[GM], sl[GM];

    int tid = threadIdx.x;
    int g0 = tid >> 7;          // gate of row r0 (0 or 1); r1 gate = g0+2
    int u  = tid & 127;
    int r0 = tid, r1 = tid + 256;

    int grp = (NGRP - 1) - blockIdx.x;   // longest groups scheduled first
    if (tid < GM) {
        int n = g_order[grp * GM + tid];
        sn[tid] = n;
        sl[tid] = g_len[n];
    }

    // stage smem weight part (p2 = 0..21)
    const float4* Wk4 = (const float4*)g_Wk;
    float4* sW4 = (float4*)sW;
    for (int i = tid; i < 22 * 512; i += 256) sW4[i] = Wk4[i];
    // zero both h buffers
    for (int i = tid; i < 2048; i += 256) shf[i] = 0.0f;

    // register weight part (p2 = 22..31)
    ulonglong2 wr0[10], wr1[10];
    const ulonglong2* Wk2 = (const ulonglong2*)g_Wk;
    #pragma unroll
    for (int i = 0; i < 10; i++) {
        wr0[i] = Wk2[(size_t)(22 + i) * 512 + r0];
        wr1[i] = Wk2[(size_t)(22 + i) * 512 + r1];
    }

    float wi0 = Wih[r0], bs0 = bih[r0] + bhh[r0];
    float wi1 = Wih[r1], bs1 = bih[r1] + bhh[r1];

    __syncthreads();
    int maxlen = 0;
    #pragma unroll
    for (int m = 0; m < GM; m++) maxlen = max(maxlen, sl[m]);

    #pragma unroll
    for (int m = 0; m < GM; m++)
        for (int t = tid; t < TT; t += 256) sx[m * TT + t] = x[(size_t)sn[m] * TT + t];

    // this thread's 4 cells: seqs g0, g0+2, g0+4, g0+6
    int   slen[4];
    float* hsp[4];
    float  c[4];
    #pragma unroll
    for (int k = 0; k < 4; k++) {
        int m = g0 + 2 * k;
        slen[k] = sl[m];
        hsp[k]  = g_hs + (size_t)sn[m] * TT * HH + u;
        c[k]    = 0.0f;
    }
    __syncthreads();

    for (int t = 0; t < maxlen; t++) {
        int cur = t & 1, nxt = cur ^ 1;
        const ulonglong2* hb = (const ulonglong2*)(shf + cur * 1024);

        u64 A0[8], A1[8];
        #pragma unroll
        for (int m = 0; m < 8; m++) { A0[m] = 0; A1[m] = 0; }

        #pragma unroll 2
        for (int p2 = 0; p2 < 22; p2++) {
            ulonglong2 w0 = sW[p2 * 512 + r0];
            ulonglong2 w1 = sW[p2 * 512 + r1];
            #pragma unroll
            for (int m = 0; m < 8; m++) {
                ulonglong2 h = hb[m * 32 + p2];
                A0[m] = ffma2(w0.x, h.x, A0[m]); A0[m] = ffma2(w0.y, h.y, A0[m]);
                A1[m] = ffma2(w1.x, h.x, A1[m]); A1[m] = ffma2(w1.y, h.y, A1[m]);
            }
        }
        #pragma unroll
        for (int i = 0; i < 10; i++) {
            int p2 = 22 + i;
            ulonglong2 w0 = wr0[i];
            ulonglong2 w1 = wr1[i];
            #pragma unroll
            for (int m = 0; m < 8; m++) {
                ulonglong2 h = hb[m * 32 + p2];
                A0[m] = ffma2(w0.x, h.x, A0[m]); A0[m] = ffma2(w0.y, h.y, A0[m]);
                A1[m] = ffma2(w1.x, h.x, A1[m]); A1[m] = ffma2(w1.y, h.y, A1[m]);
            }
        }

        // pre-activations for this thread's two gate-rows, 8 seqs each
        #pragma unroll
        for (int m = 0; m < 8; m++) {
            float xt = sx[m * TT + t];
            spre[((g0)     * 8 + m) * 128 + u] = f2lo(A0[m]) + f2hi(A0[m]) + xt * wi0 + bs0;
            spre[((g0 + 2) * 8 + m) * 128 + u] = f2lo(A1[m]) + f2hi(A1[m]) + xt * wi1 + bs1;
        }
        __syncthreads();

        // cell updates (4 cells per thread)
        #pragma unroll
        for (int k = 0; k < 4; k++) {
            int m = g0 + 2 * k;
            float pi = spre[(0 * 8 + m) * 128 + u];
            float pf = spre[(1 * 8 + m) * 128 + u];
            float pg = spre[(2 * 8 + m) * 128 + u];
            float po = spre[(3 * 8 + m) * 128 + u];
            c[k] = sigf(pf) * c[k] + sigf(pi) * tanh_(pg);
            float hv = sigf(po) * tanh_(c[k]);
            shf[nxt * 1024 + m * 128 + u] = hv;
            if (t < slen[k]) hsp[k][(size_t)t * HH] = hv;
        }
        __syncthreads();
    }

    // zero masked tails so the feats GEMM can ignore lengths
    #pragma unroll
    for (int k = 0; k < 4; k++)
        for (int t = slen[k]; t < TT; t++)
            hsp[k][(size_t)t * HH] = 0.0f;
}

// ---------------- kernel 5: feats GEMM (split-K, tiled, f32x2) -------------------
// psum[kz][n][j] = sum_{t in chunk} sum_h hs[n][t][h] * W1[j][t*128+h]
__global__ void __launch_bounds__(256) k_feats(const float* __restrict__ W1) {
    __shared__ __align__(16) float sh_hs[TM][HH + 4];     // padded: conflict-free
    __shared__ __align__(16) float sh_w[NINTER][HH];

    int tile = blockIdx.x;        // 0..39
    int kz = blockIdx.y;          // 0..7
    int tid = threadIdx.x;
    int s0 = tid & 15;            // rows s0 and s0+16
    int j0 = (tid >> 4) * 4;      // 4 inter cols
    u64 a0[4] = {0, 0, 0, 0};
    u64 a1[4] = {0, 0, 0, 0};

    int t0 = kz * TCHUNK;
    for (int tt = 0; tt < TCHUNK; tt++) {
        int t = t0 + tt;
        __syncthreads();
        for (int i = tid; i < TM * 32; i += 256) {
            int s = i >> 5, kq = i & 31;
            ((float4*)&sh_hs[s][0])[kq] =
                ((const float4*)(g_hs + ((size_t)(tile * TM + s) * TT + t) * HH))[kq];
        }
        for (int i = tid; i < NINTER * 32; i += 256) {
            int j = i >> 5, kq = i & 31;
            ((float4*)&sh_w[j][0])[kq] =
                ((const float4*)(W1 + (size_t)j * (TT * HH) + (size_t)t * HH))[kq];
        }
        __syncthreads();
        #pragma unroll 4
        for (int kq = 0; kq < 32; kq++) {
            ulonglong2 hA = ((const ulonglong2*)&sh_hs[s0][0])[kq];
            ulonglong2 hB = ((const ulonglong2*)&sh_hs[s0 + 16][0])[kq];
            #pragma unroll
            for (int c = 0; c < 4; c++) {
                ulonglong2 w = ((const ulonglong2*)&sh_w[j0 + c][0])[kq];
                a0[c] = ffma2(hA.x, w.x, a0[c]); a0[c] = ffma2(hA.y, w.y, a0[c]);
                a1[c] = ffma2(hB.x, w.x, a1[c]); a1[c] = ffma2(hB.y, w.y, a1[c]);
            }
        }
    }
    int srow = tile * TM;
    size_t baseA = ((size_t)kz * NN + (srow + s0)) * NINTER + j0;
    size_t baseB = ((size_t)kz * NN + (srow + s0 + 16)) * NINTER + j0;
    #pragma unroll
    for (int c = 0; c < 4; c++) {
        g_psum[baseA + c] = f2lo(a0[c]) + f2hi(a0[c]);
        g_psum[baseB + c] = f2lo(a1[c]) + f2hi(a1[c]);
    }
}

// ---------------- kernel 6: reduce split-K + bias + final linear -----------------
__global__ void __launch_bounds__(256) k_final(
    const float* __restrict__ b1, const float* __restrict__ W2,
    const float* __restrict__ b2, float* __restrict__ out)
{
    __shared__ float sf[SS * NINTER];   // 1280 feats for this batch
    __shared__ float r0[256], r1[256];
    int b = blockIdx.x, tid = threadIdx.x;

    for (int i = tid; i < SS * NINTER; i += 256) {
        int s = i / NINTER, j = i % NINTER;
        size_t nq = (size_t)b * SS + s;
        float v = b1[j];
        #pragma unroll
        for (int kz = 0; kz < KSPLIT; kz++)
            v += g_psum[((size_t)kz * NN + nq) * NINTER + j];
        sf[i] = v;
    }
    __syncthreads();
    float p0 = 0.f, p1 = 0.f;
    for (int i = tid; i < SS * NINTER; i += 256) {
        float f = sf[i];
        p0 += f * W2[i];
        p1 += f * W2[SS * NINTER + i];
    }
    r0[tid] = p0; r1[tid] = p1;
    __syncthreads();
    for (int off = 128; off; off >>= 1) {
        if (tid < off) { r0[tid] += r0[tid + off]; r1[tid] += r1[tid + off]; }
        __syncthreads();
    }
    if (tid == 0) {
        out[b * 2 + 0] = r0[0] + b2[0];
        out[b * 2 + 1] = r1[0] + b2[1];
    }
}

// ---------------- launch ----------------------------------------------------------
extern "C" void kernel_launch(void* const* d_in, const int* in_sizes, int n_in,
                              void* d_out, int out_size)
{
    const float* x   = (const float*)d_in[0];
    // d_in[1] = metadata (unused by the reference computation)
    const float* Wih = (const float*)d_in[2];
    const float* Whh = (const float*)d_in[3];
    const float* bih = (const float*)d_in[4];
    const float* bhh = (const float*)d_in[5];
    const float* W1  = (const float*)d_in[6];
    const float* b1  = (const float*)d_in[7];
    const float* W2  = (const float*)d_in[8];
    const float* b2  = (const float*)d_in[9];
    float* out = (float*)d_out;

    cudaFuncSetAttribute(k_lstm, cudaFuncAttributeMaxDynamicSharedMemorySize, LSTM_SMEM);

    k_lens<<<NN, 32>>>(x);
    k_sort<<<1, 256>>>();
    k_wt<<<64, 256>>>(Whh);
    k_lstm<<<NGRP, 256, LSTM_SMEM>>>(x, Wih, bih, bhh);
    k_feats<<<dim3(40, KSPLIT), 256>>>(W1);
    k_final<<<BB, 256>>>(b1, W2, b2, out);
}